// round 9
// baseline (speedup 1.0000x reference)
#include <cuda_runtime.h>
#include <cstdint>

#define NC      32
#define NSTEPS  32
#define DDIM    30
#define BLOCK   256
#define PPT     4     // chains per thread: 2 via SHFL, 2 via LDS.64

// 16-slot float2 table: tab[cell][slot] = (T00,T01), slot = lane&15.
// Entry 8B, slot stride 8B, cell stride 128B, table 4KB.
// LDS.64 runs in two 16-lane phases; within a phase slot*8 covers all 32
// banks once and cell*128 shifts by 0 mod 32 banks -> conflict-free.
#define TAB_FLTS    (NC * 16 * 2)     // 4KB
#define SLACK_FLTS  1024              // 4KB slack for runtime 4096-alignment

__global__ __launch_bounds__(BLOCK)
void cpab_kernel(const float* __restrict__ points,
                 const float* __restrict__ theta,
                 const float* __restrict__ basis,
                 float* __restrict__ out,
                 int n_points)
{
    __shared__ float sbuf[TAB_FLTS + SLACK_FLTS];
    __shared__ float s0[NC];
    __shared__ float s1[NC];

    const int t    = blockIdx.y;
    const int tid  = threadIdx.x;
    const int lane = tid & 31;

    // Runtime 4096-aligned table base; per-thread constant base | slot*8.
    uint32_t sbase = (uint32_t)__cvta_generic_to_shared(sbuf);
    uint32_t abase = (sbase + 4095u) & ~4095u;
    uint32_t C = abase | ((uint32_t)(tid & 15) << 3);

    // --- 32 per-cell step transforms for this theta ---
    if (tid < NC) {
        const float dT = 1.0f / (float)NSTEPS;
        const float* __restrict__ ba = basis + (2 * tid)     * DDIM;
        const float* __restrict__ bb = basis + (2 * tid + 1) * DDIM;
        const float* __restrict__ th = theta + t * DDIM;
        float a = 0.0f, b = 0.0f;
        #pragma unroll
        for (int j = 0; j < DDIM; ++j) {
            float tj = th[j];
            a = fmaf(ba[j], tj, a);
            b = fmaf(bb[j], tj, b);
        }
        a *= dT;
        b *= dT;
        float ea  = expf(a);
        float phi = (fabsf(a) < 1e-6f) ? (1.0f + 0.5f * a) : (expm1f(a) / a);
        s0[tid] = ea;
        s1[tid] = b * phi;
    }
    __syncthreads();

    // LDS table (16-slot replication)
    {
        float2* tab = (float2*)(sbuf + ((abase - sbase) >> 2));
        #pragma unroll
        for (int i = tid; i < NC * 16; i += BLOCK) {
            int cell = i >> 4;
            tab[i] = make_float2(s0[cell], s1[cell]);
        }
    }
    __syncthreads();

    // SHFL table: lane l holds cell l's transform.
    const float T0 = s0[lane];
    const float T1 = s1[lane];

    // --- Main integration: 4 chains/thread, 2 SHFL-path + 2 LDS-path ---
    const int base = blockIdx.x * (BLOCK * PPT) + tid;

    float x[PPT];
    #pragma unroll
    for (int k = 0; k < PPT; ++k) {
        int idx = base + k * BLOCK;
        x[k] = (idx < n_points) ? points[idx] : 0.0f;
    }

    #pragma unroll 4
    for (int s = 0; s < NSTEPS; ++s) {
        // indices for all 4 chains first (independent alu work up front)
        int bi[PPT];
        #pragma unroll
        for (int k = 0; k < PPT; ++k) {
            // bits = 0x4B000000 + floor(x*32 or x*4096), exact (RZ fma).
            float scale = (k < 2) ? 32.0f : 4096.0f;
            int b = (int)__float_as_uint(__fmaf_rz(x[k], scale, 8388608.0f));
            b = max(b, 0x4B000000);
            b = min(b, (k < 2) ? 0x4B00001F : 0x4B000FFF);
            bi[k] = b;
        }

        // LDS-path gathers (issue early: long-scoreboard ops)
        float l0[2], l1[2];
        #pragma unroll
        for (int k = 0; k < 2; ++k) {
            uint32_t addr = ((uint32_t)bi[2 + k] & 0x0F80u) | C;
            asm volatile("ld.shared.v2.f32 {%0,%1}, [%2];"
                         : "=f"(l0[k]), "=f"(l1[k]) : "r"(addr));
        }

        // SHFL-path gathers (low 5 bits of bi == cell; shfl wraps mod 32)
        float h0[2], h1[2];
        #pragma unroll
        for (int k = 0; k < 2; ++k) {
            h0[k] = __shfl_sync(0xFFFFFFFFu, T0, bi[k]);
            h1[k] = __shfl_sync(0xFFFFFFFFu, T1, bi[k]);
        }

        x[0] = fmaf(h0[0], x[0], h1[0]);
        x[1] = fmaf(h0[1], x[1], h1[1]);
        x[2] = fmaf(l0[0], x[2], l1[0]);
        x[3] = fmaf(l0[1], x[3], l1[1]);
    }

    float* __restrict__ o = out + (size_t)t * (size_t)n_points;
    #pragma unroll
    for (int k = 0; k < PPT; ++k) {
        int idx = base + k * BLOCK;
        if (idx < n_points) o[idx] = x[k];
    }
}

extern "C" void kernel_launch(void* const* d_in, const int* in_sizes, int n_in,
                              void* d_out, int out_size)
{
    const float* points = (const float*)d_in[0];  // [1, n_points]
    const float* theta  = (const float*)d_in[1];  // [n_theta, 30]
    const float* basis  = (const float*)d_in[2];  // [64, 30]
    float* out = (float*)d_out;                   // [n_theta, 1, n_points]

    const int n_points = in_sizes[0];
    const int n_theta  = in_sizes[1] / DDIM;

    dim3 grid((n_points + BLOCK * PPT - 1) / (BLOCK * PPT), n_theta);
    cpab_kernel<<<grid, BLOCK>>>(points, theta, basis, out, n_points);
}

// round 10
// speedup vs baseline: 1.0013x; 1.0013x over previous
#include <cuda_runtime.h>
#include <cstdint>

#define NC      32
#define NSTEPS  32
#define DDIM    30
#define BLOCK   256
#define PPT     4     // independent chains per thread; grid ~2048 blocks

__global__ __launch_bounds__(BLOCK)
void cpab_kernel(const float* __restrict__ points,
                 const float* __restrict__ theta,
                 const float* __restrict__ basis,
                 float* __restrict__ out,
                 int n_points)
{
    __shared__ float s0[NC];
    __shared__ float s1[NC];

    const int t    = blockIdx.y;
    const int tid  = threadIdx.x;
    const int lane = tid & 31;

    // --- 32 per-cell step transforms for this theta ---
    if (tid < NC) {
        const float dT = 1.0f / (float)NSTEPS;
        const float* __restrict__ ba = basis + (2 * tid)     * DDIM;
        const float* __restrict__ bb = basis + (2 * tid + 1) * DDIM;
        const float* __restrict__ th = theta + t * DDIM;
        float a = 0.0f, b = 0.0f;
        #pragma unroll
        for (int j = 0; j < DDIM; ++j) {
            float tj = th[j];
            a = fmaf(ba[j], tj, a);
            b = fmaf(bb[j], tj, b);
        }
        a *= dT;
        b *= dT;
        float ea  = expf(a);
        float phi = (fabsf(a) < 1e-6f) ? (1.0f + 0.5f * a) : (expm1f(a) / a);
        s0[tid] = ea;
        s1[tid] = b * phi;
    }
    __syncthreads();

    // Table lives in registers: lane l holds cell l's transform.
    const float T0 = s0[lane];
    const float T1 = s1[lane];

    // --- Main integration: 4 independent chains per thread ---
    const int base = blockIdx.x * (BLOCK * PPT) + tid;

    float x[PPT];
    #pragma unroll
    for (int k = 0; k < PPT; ++k) {
        int idx = base + k * BLOCK;
        x[k] = (idx < n_points) ? points[idx] : 0.0f;
    }

    #pragma unroll 4
    for (int s = 0; s < NSTEPS; ++s) {
        #pragma unroll
        for (int k = 0; k < PPT; ++k) {
            // bits = 0x4B000000 + floor(x*32), exact (RZ fma, positive sum).
            // Low 5 bits == cell index; shfl wraps srcLane mod 32.
            int bi = (int)__float_as_uint(__fmaf_rz(x[k], 32.0f, 8388608.0f));
            bi = max(bi, 0x4B000000);          // x < 0  -> cell 0
            bi = min(bi, 0x4B00001F);          // x >= 1 -> cell 31
            float t0 = __shfl_sync(0xFFFFFFFFu, T0, bi);
            float t1 = __shfl_sync(0xFFFFFFFFu, T1, bi);
            x[k] = fmaf(t0, x[k], t1);
        }
    }

    float* __restrict__ o = out + (size_t)t * (size_t)n_points;
    #pragma unroll
    for (int k = 0; k < PPT; ++k) {
        int idx = base + k * BLOCK;
        if (idx < n_points) o[idx] = x[k];
    }
}

extern "C" void kernel_launch(void* const* d_in, const int* in_sizes, int n_in,
                              void* d_out, int out_size)
{
    const float* points = (const float*)d_in[0];  // [1, n_points]
    const float* theta  = (const float*)d_in[1];  // [n_theta, 30]
    const float* basis  = (const float*)d_in[2];  // [64, 30]
    float* out = (float*)d_out;                   // [n_theta, 1, n_points]

    const int n_points = in_sizes[0];
    const int n_theta  = in_sizes[1] / DDIM;

    dim3 grid((n_points + BLOCK * PPT - 1) / (BLOCK * PPT), n_theta);
    cpab_kernel<<<grid, BLOCK>>>(points, theta, basis, out, n_points);
}

// round 11
// speedup vs baseline: 1.0115x; 1.0102x over previous
#include <cuda_runtime.h>
#include <cstdint>

#define NC      32
#define NSTEPS  32
#define DDIM    30
#define BLOCK   256
#define PPT     8     // independent chains per thread (R8 winning shape)

__global__ __launch_bounds__(BLOCK)
void cpab_kernel(const float* __restrict__ points,
                 const float* __restrict__ theta,
                 const float* __restrict__ basis,
                 float* __restrict__ out,
                 int n_points)
{
    __shared__ float s0[NC];
    __shared__ float s1[NC];

    const int t    = blockIdx.y;
    const int tid  = threadIdx.x;
    const int lane = tid & 31;

    // --- 32 per-cell step transforms for this theta ---
    if (tid < NC) {
        const float dT = 1.0f / (float)NSTEPS;
        const float* __restrict__ ba = basis + (2 * tid)     * DDIM;
        const float* __restrict__ bb = basis + (2 * tid + 1) * DDIM;
        const float* __restrict__ th = theta + t * DDIM;
        float a = 0.0f, b = 0.0f;
        #pragma unroll
        for (int j = 0; j < DDIM; ++j) {
            float tj = th[j];
            a = fmaf(ba[j], tj, a);
            b = fmaf(bb[j], tj, b);
        }
        a *= dT;
        b *= dT;
        float ea  = expf(a);
        float phi = (fabsf(a) < 1e-6f) ? (1.0f + 0.5f * a) : (expm1f(a) / a);
        s0[tid] = ea;
        s1[tid] = b * phi;
    }
    __syncthreads();

    // Table lives in registers: lane l holds cell l's transform.
    const float T0 = s0[lane];
    const float T1 = s1[lane];

    // --- Main integration: 8 independent chains, fully unrolled, phase-batched ---
    const int base = blockIdx.x * (BLOCK * PPT) + tid;

    float x[PPT];
    #pragma unroll
    for (int k = 0; k < PPT; ++k) {
        int idx = base + k * BLOCK;
        x[k] = (idx < n_points) ? points[idx] : 0.0f;
    }

    #pragma unroll
    for (int s = 0; s < NSTEPS; ++s) {
        // Phase 1: all 8 index computations (independent fma/alu work)
        int bi[PPT];
        #pragma unroll
        for (int k = 0; k < PPT; ++k) {
            // bits = 0x4B000000 + floor(x*32), exact (RZ fma, positive sum).
            // Low 5 bits == cell index; shfl wraps srcLane mod 32.
            int b = (int)__float_as_uint(__fmaf_rz(x[k], 32.0f, 8388608.0f));
            b = max(b, 0x4B000000);            // x < 0  -> cell 0
            b = min(b, 0x4B00001F);            // x >= 1 -> cell 31
            bi[k] = b;
        }

        // Phase 2: all 16 shuffles back-to-back (keep the MIO queue full)
        float t0[PPT], t1[PPT];
        #pragma unroll
        for (int k = 0; k < PPT; ++k)
            t0[k] = __shfl_sync(0xFFFFFFFFu, T0, bi[k]);
        #pragma unroll
        for (int k = 0; k < PPT; ++k)
            t1[k] = __shfl_sync(0xFFFFFFFFu, T1, bi[k]);

        // Phase 3: all 8 applies
        #pragma unroll
        for (int k = 0; k < PPT; ++k)
            x[k] = fmaf(t0[k], x[k], t1[k]);
    }

    float* __restrict__ o = out + (size_t)t * (size_t)n_points;
    #pragma unroll
    for (int k = 0; k < PPT; ++k) {
        int idx = base + k * BLOCK;
        if (idx < n_points) o[idx] = x[k];
    }
}

extern "C" void kernel_launch(void* const* d_in, const int* in_sizes, int n_in,
                              void* d_out, int out_size)
{
    const float* points = (const float*)d_in[0];  // [1, n_points]
    const float* theta  = (const float*)d_in[1];  // [n_theta, 30]
    const float* basis  = (const float*)d_in[2];  // [64, 30]
    float* out = (float*)d_out;                   // [n_theta, 1, n_points]

    const int n_points = in_sizes[0];
    const int n_theta  = in_sizes[1] / DDIM;

    dim3 grid((n_points + BLOCK * PPT - 1) / (BLOCK * PPT), n_theta);
    cpab_kernel<<<grid, BLOCK>>>(points, theta, basis, out, n_points);
}